// round 11
// baseline (speedup 1.0000x reference)
#include <cuda_runtime.h>

#define NH   10
#define NL   10
#define TPB  128

// ---- raw weight layout in cw (float offsets; all pair offsets even) ----
#define OFF_W0   0
#define OFF_B0   30
#define OFF_W1   40
#define OFF_B1   140
#define OFF_WR1  150
#define OFF_BR1  1150
#define OFF_WR2  1250
#define OFF_BR2  2250
#define OFF_WR3  2350
#define OFF_BR3  3350
#define OFF_W8   3450
#define OFF_B8   3550
#define OFF_W9   3560
#define OFF_B9   3570
#define CW_TOTAL 3572
#define B23_OFF  3572            // (BR2+BR3) dup pairs, [10][10]
#define SW_TOTAL 3672            // dup-table length in float2

__constant__ __align__(16) float  cw[CW_TOTAL];
__constant__ __align__(16) float2 cdup[SW_TOTAL];          // duplicated pairs (w,w)
__device__   __align__(16) float2 dupbuf[SW_TOTAL];        // staging for cdup

__device__ __forceinline__ float2 f2(float x, float y) { return make_float2(x, y); }

// packed fp32x2 FMA (Blackwell FFMA2)
__device__ __forceinline__ float2 ffma2(float2 a, float2 b, float2 c) {
    float2 d;
    asm("{\n\t"
        ".reg .b64 ra, rb, rc, rd;\n\t"
        "mov.b64 ra, {%2, %3};\n\t"
        "mov.b64 rb, {%4, %5};\n\t"
        "mov.b64 rc, {%6, %7};\n\t"
        "fma.rn.f32x2 rd, ra, rb, rc;\n\t"
        "mov.b64 {%0, %1}, rd;\n\t"
        "}"
        : "=f"(d.x), "=f"(d.y)
        : "f"(a.x), "f"(a.y), "f"(b.x), "f"(b.y), "f"(c.x), "f"(c.y));
    return d;
}
__device__ __forceinline__ float2 relu2(float2 v) {
    return f2(fmaxf(v.x, 0.0f), fmaxf(v.y, 0.0f));
}

// load 2 dup pairs (16B) from SMEM dup table
__device__ __forceinline__ float4 lds4(const float2* __restrict__ sm, int i) {
    return *reinterpret_cast<const float4*>(&sm[i]);
}

// dense + relu, ONE point-pair per thread (reads all h before writing -> in-place safe)
template<int K>
__device__ __forceinline__ void dense(int Woff, int Boff, const float2* __restrict__ sm,
                                      const float2 (&h)[K], float2 (&out)[NH])
{
    float2 acc[NH];
#pragma unroll
    for (int j2 = 0; j2 < NH/2; j2++) {            // k=0 folds bias as addend
        float4 b = lds4(sm, Boff + 2*j2);
        float4 w = lds4(sm, Woff + 2*j2);
        acc[2*j2+0] = ffma2(h[0], f2(w.x, w.y), f2(b.x, b.y));
        acc[2*j2+1] = ffma2(h[0], f2(w.z, w.w), f2(b.z, b.w));
    }
#pragma unroll
    for (int k = 1; k < K; k++) {
#pragma unroll
        for (int j2 = 0; j2 < NH/2; j2++) {
            float4 w = lds4(sm, Woff + k*NH + 2*j2);
            acc[2*j2+0] = ffma2(h[k], f2(w.x, w.y), acc[2*j2+0]);
            acc[2*j2+1] = ffma2(h[k], f2(w.z, w.w), acc[2*j2+1]);
        }
    }
#pragma unroll
    for (int j = 0; j < NH; j++)
        out[j] = relu2(acc[j]);
}

// residual: out = relu( h1 @ W3 + h0 @ W2 + (B2+B3) ), all from SMEM
__device__ __forceinline__ void dense_res(int W3o, int W2o, int B23o,
                                          const float2* __restrict__ sm,
                                          const float2 (&h1)[NH],
                                          const float2 (&h0)[NH],
                                          float2 (&out)[NH])
{
    float2 acc[NH];
#pragma unroll
    for (int j2 = 0; j2 < NH/2; j2++) {
        float4 b = lds4(sm, B23o + 2*j2);
        float4 w = lds4(sm, W3o + 2*j2);             // k=0 of W3
        acc[2*j2+0] = ffma2(h1[0], f2(w.x, w.y), f2(b.x, b.y));
        acc[2*j2+1] = ffma2(h1[0], f2(w.z, w.w), f2(b.z, b.w));
    }
#pragma unroll
    for (int k = 1; k < NH; k++) {
#pragma unroll
        for (int j2 = 0; j2 < NH/2; j2++) {
            float4 w = lds4(sm, W3o + k*NH + 2*j2);
            acc[2*j2+0] = ffma2(h1[k], f2(w.x, w.y), acc[2*j2+0]);
            acc[2*j2+1] = ffma2(h1[k], f2(w.z, w.w), acc[2*j2+1]);
        }
    }
#pragma unroll
    for (int k = 0; k < NH; k++) {
#pragma unroll
        for (int j2 = 0; j2 < NH/2; j2++) {
            float4 w = lds4(sm, W2o + k*NH + 2*j2);
            acc[2*j2+0] = ffma2(h0[k], f2(w.x, w.y), acc[2*j2+0]);
            acc[2*j2+1] = ffma2(h0[k], f2(w.z, w.w), acc[2*j2+1]);
        }
    }
#pragma unroll
    for (int j = 0; j < NH; j++)
        out[j] = relu2(acc[j]);
}

__global__ void prep_kernel()
{
    for (int i = threadIdx.x; i < CW_TOTAL; i += blockDim.x) {
        float w = cw[i];
        dupbuf[i] = make_float2(w, w);
    }
    for (int i = threadIdx.x; i < 100; i += blockDim.x) {
        float s = cw[OFF_BR2 + i] + cw[OFF_BR3 + i];
        dupbuf[B23_OFF + i] = make_float2(s, s);
    }
}

__global__ void __launch_bounds__(TPB, 5)
resnet_kernel(const float2* __restrict__ x2, float2* __restrict__ out2, int nthreads)
{
    // SMEM dup table (whole table; all weight loads come from here)
    __shared__ __align__(16) float2 sw[SW_TOTAL];
    for (int i = threadIdx.x; i < SW_TOTAL; i += TPB) sw[i] = cdup[i];
    __syncthreads();

    int t = blockIdx.x * TPB + threadIdx.x;
    if (t >= nthreads) return;

    // 2 points = 6 contiguous floats = 3 aligned float2 loads
    float2 d0 = x2[3*t + 0];   // (p0.x, p0.y)
    float2 d1 = x2[3*t + 1];   // (p0.z, p1.x)
    float2 d2 = x2[3*t + 2];   // (p1.y, p1.z)
    // point-pair packed input: xin[k] = (pt0[k], pt1[k])
    float2 xin[3] = { f2(d0.x, d1.y), f2(d0.y, d2.x), f2(d1.x, d2.y) };

    float2 h [NH];
    float2 h1[NH];

    dense<3 >(OFF_W0, OFF_B0, sw, xin, h);
    dense<NH>(OFF_W1, OFF_B1, sw, h,   h);

#pragma unroll 1
    for (int l = 0; l < NL; l++) {
        dense<NH>(OFF_WR1 + l*100, OFF_BR1 + l*10, sw, h, h1);
        dense_res(OFF_WR3 + l*100, OFF_WR2 + l*100, B23_OFF + l*10, sw, h1, h, h);
    }

    dense<NH>(OFF_W8, OFF_B8, sw, h, h);

    // final [10]->[1], point-pair packed
    float2 o = sw[OFF_B9];     // (b9, b9)
#pragma unroll
    for (int k = 0; k < NH; k++)
        o = ffma2(h[k], sw[OFF_W9 + k], o);
    out2[t] = o;               // (out_pt0, out_pt1) contiguous
}

extern "C" void kernel_launch(void* const* d_in, const int* in_sizes, int n_in,
                              void* d_out, int out_size)
{
    // stage raw weights into constant memory (D2D async copies: graph-capturable)
    static const int idx[14] = {1, 2, 3, 4, 5, 6, 7, 8, 9, 10, 11, 12, 13, 14};
    static const int off[14] = {OFF_W0, OFF_B0, OFF_W1, OFF_B1,
                                OFF_WR1, OFF_BR1, OFF_WR2, OFF_BR2, OFF_WR3, OFF_BR3,
                                OFF_W8, OFF_B8, OFF_W9, OFF_B9};
    static const int cnt[14] = {30, 10, 100, 10, 1000, 100, 1000, 100, 1000, 100, 100, 10, 10, 1};
    for (int i = 0; i < 14; i++) {
        cudaMemcpyToSymbolAsync(cw, d_in[idx[i]], (size_t)cnt[i] * sizeof(float),
                                (size_t)off[i] * sizeof(float),
                                cudaMemcpyDeviceToDevice, 0);
    }

    // build duplicated-pair table on device, then stage it into constant memory
    prep_kernel<<<1, 512>>>();
    void* dup_ptr = nullptr;
    cudaGetSymbolAddress(&dup_ptr, dupbuf);
    cudaMemcpyToSymbolAsync(cdup, dup_ptr, SW_TOTAL * sizeof(float2), 0,
                            cudaMemcpyDeviceToDevice, 0);

    int npts     = in_sizes[0] / 3;   // x is [N,3]
    int nthreads = npts / 2;          // 2 points per thread
    int nblocks  = (nthreads + TPB - 1) / TPB;
    resnet_kernel<<<nblocks, TPB>>>((const float2*)d_in[0], (float2*)d_out, nthreads);
}

// round 12
// speedup vs baseline: 2.2374x; 2.2374x over previous
#include <cuda_runtime.h>

#define NH   10
#define NL   10
#define TPB  128

// ---- raw weight layout in cw (float offsets) ----
#define OFF_W0   0
#define OFF_B0   30
#define OFF_W1   40
#define OFF_B1   140
#define OFF_WR1  150
#define OFF_BR1  1150
#define OFF_WR2  1250
#define OFF_BR2  2250
#define OFF_WR3  2350
#define OFF_BR3  3350
#define OFF_W8   3450
#define OFF_B8   3550
#define OFF_W9   3560
#define OFF_B9   3570
#define CW_TOTAL 3572
// cdup float2 regions
#define B23_OFF  3572            // (BR2+BR3) dup pairs, [10][10]
#define CDUP_TOT 3672

// SMEM dup table (float2 offsets, all even -> 16B-aligned float4 loads)
#define SM_W2   0                // [10][10][10] -> 1000
#define SM_W3   1000             // [10][10][10] -> 1000
#define SM_W8   2000             // [10][10]     -> 100
#define SM_B8   2100             // [10]
#define SM_B23  2110             // [10][10]     -> 100
#define SM_W0   2210             // [3][10]      -> 30
#define SM_B0   2240             // [10]
#define SM_W1   2250             // [10][10]     -> 100
#define SM_B1   2350             // [10]
#define SM_TOT  2360

__constant__ __align__(16) float  cw[CW_TOTAL];
__constant__ __align__(16) float2 cdup[CDUP_TOT];          // duplicated pairs (w,w)
__device__   __align__(16) float2 dupbuf[CDUP_TOT];        // staging for cdup

__device__ __forceinline__ float2 f2(float x, float y) { return make_float2(x, y); }

// packed fp32x2 FMA (Blackwell FFMA2)
__device__ __forceinline__ float2 ffma2(float2 a, float2 b, float2 c) {
    float2 d;
    asm("{\n\t"
        ".reg .b64 ra, rb, rc, rd;\n\t"
        "mov.b64 ra, {%2, %3};\n\t"
        "mov.b64 rb, {%4, %5};\n\t"
        "mov.b64 rc, {%6, %7};\n\t"
        "fma.rn.f32x2 rd, ra, rb, rc;\n\t"
        "mov.b64 {%0, %1}, rd;\n\t"
        "}"
        : "=f"(d.x), "=f"(d.y)
        : "f"(a.x), "f"(a.y), "f"(b.x), "f"(b.y), "f"(c.x), "f"(c.y));
    return d;
}
__device__ __forceinline__ float2 relu2(float2 v) {
    return f2(fmaxf(v.x, 0.0f), fmaxf(v.y, 0.0f));
}

// ONE dup pair (8B) from constant — warp-uniform 64-bit load, LDCU-promotable
__device__ __forceinline__ float2 ldc2(int i) {
    union { unsigned long long u; float2 f; } v;
    v.u = *reinterpret_cast<const unsigned long long*>(&cdup[i]);
    return v.f;
}
// two dup pairs (16B) from SMEM
__device__ __forceinline__ float4 lds4(const float2* __restrict__ sm, int i) {
    return *reinterpret_cast<const float4*>(&sm[i]);
}

// dense + relu via SMEM (LDS.128 stream); in-place safe
template<int K>
__device__ __forceinline__ void dense_s(int Woff, int Boff, const float2* __restrict__ sm,
                                        const float2 (&h)[2][K], float2 (&out)[2][NH])
{
    float2 acc[2][NH];
#pragma unroll
    for (int j2 = 0; j2 < NH/2; j2++) {            // k=0 folds bias as addend
        float4 b = lds4(sm, Boff + 2*j2);
        float4 w = lds4(sm, Woff + 2*j2);
#pragma unroll
        for (int pp = 0; pp < 2; pp++) {
            acc[pp][2*j2+0] = ffma2(h[pp][0], f2(w.x, w.y), f2(b.x, b.y));
            acc[pp][2*j2+1] = ffma2(h[pp][0], f2(w.z, w.w), f2(b.z, b.w));
        }
    }
#pragma unroll
    for (int k = 1; k < K; k++) {
#pragma unroll
        for (int j2 = 0; j2 < NH/2; j2++) {
            float4 w = lds4(sm, Woff + k*NH + 2*j2);
#pragma unroll
            for (int pp = 0; pp < 2; pp++) {
                acc[pp][2*j2+0] = ffma2(h[pp][k], f2(w.x, w.y), acc[pp][2*j2+0]);
                acc[pp][2*j2+1] = ffma2(h[pp][k], f2(w.z, w.w), acc[pp][2*j2+1]);
            }
        }
    }
#pragma unroll
    for (int pp = 0; pp < 2; pp++)
#pragma unroll
        for (int j = 0; j < NH; j++)
            out[pp][j] = relu2(acc[pp][j]);
}

// dense + relu via constant 8B loads (LDCU stream); in-place safe
template<int K>
__device__ __forceinline__ void dense_c(int Woff, int Boff,
                                        const float2 (&h)[2][K], float2 (&out)[2][NH])
{
    float2 acc[2][NH];
#pragma unroll
    for (int j = 0; j < NH; j++) {                 // k=0 folds bias as addend
        float2 b = ldc2(Boff + j);
        float2 w = ldc2(Woff + j);
#pragma unroll
        for (int pp = 0; pp < 2; pp++)
            acc[pp][j] = ffma2(h[pp][0], w, b);
    }
#pragma unroll
    for (int k = 1; k < K; k++) {
#pragma unroll
        for (int j = 0; j < NH; j++) {
            float2 w = ldc2(Woff + k*NH + j);
#pragma unroll
            for (int pp = 0; pp < 2; pp++)
                acc[pp][j] = ffma2(h[pp][k], w, acc[pp][j]);
        }
    }
#pragma unroll
    for (int pp = 0; pp < 2; pp++)
#pragma unroll
        for (int j = 0; j < NH; j++)
            out[pp][j] = relu2(acc[pp][j]);
}

// residual: out = relu( h1 @ W3 + h0 @ W2 + (B2+B3) ) — SMEM (LDS.128) stream
__device__ __forceinline__ void dense_res(int W3o, int W2o, int B23o,
                                          const float2* __restrict__ sm,
                                          const float2 (&h1)[2][NH],
                                          const float2 (&h0)[2][NH],
                                          float2 (&out)[2][NH])
{
    float2 acc[2][NH];
#pragma unroll
    for (int j2 = 0; j2 < NH/2; j2++) {
        float4 b = lds4(sm, B23o + 2*j2);
        float4 w = lds4(sm, W3o + 2*j2);       // k=0 of W3
#pragma unroll
        for (int pp = 0; pp < 2; pp++) {
            acc[pp][2*j2+0] = ffma2(h1[pp][0], f2(w.x, w.y), f2(b.x, b.y));
            acc[pp][2*j2+1] = ffma2(h1[pp][0], f2(w.z, w.w), f2(b.z, b.w));
        }
    }
#pragma unroll
    for (int k = 1; k < NH; k++) {
#pragma unroll
        for (int j2 = 0; j2 < NH/2; j2++) {
            float4 w = lds4(sm, W3o + k*NH + 2*j2);
#pragma unroll
            for (int pp = 0; pp < 2; pp++) {
                acc[pp][2*j2+0] = ffma2(h1[pp][k], f2(w.x, w.y), acc[pp][2*j2+0]);
                acc[pp][2*j2+1] = ffma2(h1[pp][k], f2(w.z, w.w), acc[pp][2*j2+1]);
            }
        }
    }
#pragma unroll
    for (int k = 0; k < NH; k++) {
#pragma unroll
        for (int j2 = 0; j2 < NH/2; j2++) {
            float4 w = lds4(sm, W2o + k*NH + 2*j2);
#pragma unroll
            for (int pp = 0; pp < 2; pp++) {
                acc[pp][2*j2+0] = ffma2(h0[pp][k], f2(w.x, w.y), acc[pp][2*j2+0]);
                acc[pp][2*j2+1] = ffma2(h0[pp][k], f2(w.z, w.w), acc[pp][2*j2+1]);
            }
        }
    }
#pragma unroll
    for (int pp = 0; pp < 2; pp++)
#pragma unroll
        for (int j = 0; j < NH; j++)
            out[pp][j] = relu2(acc[pp][j]);
}

__global__ void prep_kernel()
{
    for (int i = threadIdx.x; i < CW_TOTAL; i += blockDim.x) {
        float w = cw[i];
        dupbuf[i] = make_float2(w, w);
    }
    for (int i = threadIdx.x; i < 100; i += blockDim.x) {
        float s = cw[OFF_BR2 + i] + cw[OFF_BR3 + i];
        dupbuf[B23_OFF + i] = make_float2(s, s);
    }
}

__global__ void __launch_bounds__(TPB, 4)
resnet_kernel(const float4* __restrict__ x4, float4* __restrict__ out4, int nthreads)
{
    // SMEM dup table: W2, W3, W8+B8, B23, W0+B0, W1+B1  (the LDS stream)
    __shared__ __align__(16) float2 sw[SM_TOT];
    for (int i = threadIdx.x; i < 1000; i += TPB) {
        sw[SM_W2 + i] = cdup[OFF_WR2 + i];
        sw[SM_W3 + i] = cdup[OFF_WR3 + i];
    }
    for (int i = threadIdx.x; i < 110; i += TPB)
        sw[SM_W8 + i] = cdup[OFF_W8 + i];      // W8 then B8 (contiguous)
    for (int i = threadIdx.x; i < 100; i += TPB)
        sw[SM_B23 + i] = cdup[B23_OFF + i];
    for (int i = threadIdx.x; i < 150; i += TPB)
        sw[SM_W0 + i] = cdup[OFF_W0 + i];      // W0,B0,W1,B1 (contiguous in cw)
    __syncthreads();

    int t = blockIdx.x * TPB + threadIdx.x;
    if (t >= nthreads) return;

    // 4 points = 12 contiguous floats = 3 aligned float4 loads
    float4 a = x4[3*t + 0];
    float4 b = x4[3*t + 1];
    float4 c = x4[3*t + 2];
    // point-pair packed input: x[pp][k] = (pt_{2pp}[k], pt_{2pp+1}[k])
    float2 xin[2][3] = {
        { f2(a.x, a.w), f2(a.y, b.x), f2(a.z, b.y) },
        { f2(b.z, c.y), f2(b.w, c.z), f2(c.x, c.w) }
    };

    float2 h [2][NH];
    float2 h1[2][NH];

    dense_s<3 >(SM_W0, SM_B0, sw, xin, h);     // LDS
    dense_s<NH>(SM_W1, SM_B1, sw, h,   h);     // LDS

#pragma unroll 1
    for (int l = 0; l < NL; l++) {
        dense_c<NH>(OFF_WR1 + l*100, OFF_BR1 + l*10, h, h1);   // 8B LDC (LDCU)
        dense_res(SM_W3 + l*100, SM_W2 + l*100, SM_B23 + l*10,
                  sw, h1, h, h);                                // LDS
    }

    dense_s<NH>(SM_W8, SM_B8, sw, h, h);       // LDS

    // final [10]->[1], point-pair packed (8B LDC)
    float2 o = ldc2(OFF_B9);
#pragma unroll
    for (int k = 0; k < NH; k++)
        o = ffma2(h[0][k], ldc2(OFF_W9 + k), o);
    float2 o2 = ldc2(OFF_B9);
#pragma unroll
    for (int k = 0; k < NH; k++)
        o2 = ffma2(h[1][k], ldc2(OFF_W9 + k), o2);
    out4[t] = make_float4(o.x, o.y, o2.x, o2.y);
}

extern "C" void kernel_launch(void* const* d_in, const int* in_sizes, int n_in,
                              void* d_out, int out_size)
{
    // stage raw weights into constant memory (D2D async copies: graph-capturable)
    static const int idx[14] = {1, 2, 3, 4, 5, 6, 7, 8, 9, 10, 11, 12, 13, 14};
    static const int off[14] = {OFF_W0, OFF_B0, OFF_W1, OFF_B1,
                                OFF_WR1, OFF_BR1, OFF_WR2, OFF_BR2, OFF_WR3, OFF_BR3,
                                OFF_W8, OFF_B8, OFF_W9, OFF_B9};
    static const int cnt[14] = {30, 10, 100, 10, 1000, 100, 1000, 100, 1000, 100, 100, 10, 10, 1};
    for (int i = 0; i < 14; i++) {
        cudaMemcpyToSymbolAsync(cw, d_in[idx[i]], (size_t)cnt[i] * sizeof(float),
                                (size_t)off[i] * sizeof(float),
                                cudaMemcpyDeviceToDevice, 0);
    }

    // build duplicated-pair table on device, then stage it into constant memory
    prep_kernel<<<1, 512>>>();
    void* dup_ptr = nullptr;
    cudaGetSymbolAddress(&dup_ptr, dupbuf);
    cudaMemcpyToSymbolAsync(cdup, dup_ptr, CDUP_TOT * sizeof(float2), 0,
                            cudaMemcpyDeviceToDevice, 0);

    int npts     = in_sizes[0] / 3;   // x is [N,3]
    int nthreads = npts / 4;          // 4 points per thread
    int nblocks  = (nthreads + TPB - 1) / TPB;
    resnet_kernel<<<nblocks, TPB>>>((const float4*)d_in[0], (float4*)d_out, nthreads);
}

// round 13
// speedup vs baseline: 2.6399x; 1.1799x over previous
#include <cuda_runtime.h>

typedef unsigned long long u64;

#define NH   10
#define NL   10
#define TPB  128

// ---- raw weight layout in cw (float offsets) ----
#define OFF_W0   0
#define OFF_B0   30
#define OFF_W1   40
#define OFF_B1   140
#define OFF_WR1  150
#define OFF_BR1  1150
#define OFF_WR2  1250
#define OFF_BR2  2250
#define OFF_WR3  2350
#define OFF_BR3  3350
#define OFF_W8   3450
#define OFF_B8   3550
#define OFF_W9   3560
#define OFF_B9   3570
#define CW_TOTAL 3572
// cdup float2 regions (index = float2 slot)
#define B23_OFF  3572            // (BR2+BR3) dup pairs, [10][10]
#define CDUP_TOT 3672

__constant__ __align__(16) float  cw[CW_TOTAL];
__constant__ __align__(16) float2 cdup[CDUP_TOT];          // duplicated pairs (w,w)
__device__   __align__(16) float2 dupbuf[CDUP_TOT];        // staging for cdup

// ---- u64-domain packed fp32x2 helpers (R1-style: value never leaves b64) ----
__device__ __forceinline__ u64 pk2(float lo, float hi) {
    u64 r; asm("mov.b64 %0, {%1, %2};" : "=l"(r) : "f"(lo), "f"(hi)); return r;
}
__device__ __forceinline__ void up2(u64 v, float& lo, float& hi) {
    asm("mov.b64 {%0, %1}, %2;" : "=f"(lo), "=f"(hi) : "l"(v));
}
__device__ __forceinline__ u64 fma2(u64 a, u64 b, u64 c) {
    u64 d; asm("fma.rn.f32x2 %0, %1, %2, %3;" : "=l"(d) : "l"(a), "l"(b), "l"(c)); return d;
}
// packed relu without leaving the pair's registers (movs coalesce at allocation)
__device__ __forceinline__ u64 relu2(u64 v) {
    u64 r;
    asm("{\n\t"
        ".reg .f32 lo, hi;\n\t"
        "mov.b64 {lo, hi}, %1;\n\t"
        "max.f32 lo, lo, 0f00000000;\n\t"
        "max.f32 hi, hi, 0f00000000;\n\t"
        "mov.b64 %0, {lo, hi};\n\t"
        "}" : "=l"(r) : "l"(v));
    return r;
}
// ONE dup pair (8 bytes) from constant as a single u64 — warp-uniform address,
// value stays one b64 virtual reg (LDCU/UR-promotable), fed straight to fma2.
__device__ __forceinline__ u64 ldk(int i) {
    return *reinterpret_cast<const u64*>(&cdup[i]);
}

// dense + relu, point-pair packed, all-constant weights.
// Reads all of h before writing out -> in-place safe (out may alias h).
template<int K>
__device__ __forceinline__ void dense(int Woff, int Boff,
                                      const u64 (&h)[2][K], u64 (&out)[2][NH])
{
    u64 acc[2][NH];
#pragma unroll
    for (int j = 0; j < NH; j++) {                 // k=0 folds bias as addend
        u64 b = ldk(Boff + j);
        u64 w = ldk(Woff + j);
#pragma unroll
        for (int pp = 0; pp < 2; pp++)
            acc[pp][j] = fma2(h[pp][0], w, b);
    }
#pragma unroll
    for (int k = 1; k < K; k++) {
#pragma unroll
        for (int j = 0; j < NH; j++) {
            u64 w = ldk(Woff + k*NH + j);
#pragma unroll
            for (int pp = 0; pp < 2; pp++)
                acc[pp][j] = fma2(h[pp][k], w, acc[pp][j]);
        }
    }
#pragma unroll
    for (int pp = 0; pp < 2; pp++)
#pragma unroll
        for (int j = 0; j < NH; j++)
            out[pp][j] = relu2(acc[pp][j]);
}

// residual: out = relu( h1 @ W3 + h0 @ W2 + (B2+B3) ), all-constant weights
__device__ __forceinline__ void dense_res(int W3o, int W2o, int B23o,
                                          const u64 (&h1)[2][NH],
                                          const u64 (&h0)[2][NH],
                                          u64 (&out)[2][NH])
{
    u64 acc[2][NH];
#pragma unroll
    for (int j = 0; j < NH; j++) {                 // k=0 of W3, B23 as addend
        u64 b = ldk(B23o + j);
        u64 w = ldk(W3o + j);
#pragma unroll
        for (int pp = 0; pp < 2; pp++)
            acc[pp][j] = fma2(h1[pp][0], w, b);
    }
#pragma unroll
    for (int k = 1; k < NH; k++) {
#pragma unroll
        for (int j = 0; j < NH; j++) {
            u64 w = ldk(W3o + k*NH + j);
#pragma unroll
            for (int pp = 0; pp < 2; pp++)
                acc[pp][j] = fma2(h1[pp][k], w, acc[pp][j]);
        }
    }
#pragma unroll
    for (int k = 0; k < NH; k++) {
#pragma unroll
        for (int j = 0; j < NH; j++) {
            u64 w = ldk(W2o + k*NH + j);
#pragma unroll
            for (int pp = 0; pp < 2; pp++)
                acc[pp][j] = fma2(h0[pp][k], w, acc[pp][j]);
        }
    }
#pragma unroll
    for (int pp = 0; pp < 2; pp++)
#pragma unroll
        for (int j = 0; j < NH; j++)
            out[pp][j] = relu2(acc[pp][j]);
}

__global__ void prep_kernel()
{
    for (int i = threadIdx.x; i < CW_TOTAL; i += blockDim.x) {
        float w = cw[i];
        dupbuf[i] = make_float2(w, w);
    }
    for (int i = threadIdx.x; i < 100; i += blockDim.x) {
        float s = cw[OFF_BR2 + i] + cw[OFF_BR3 + i];
        dupbuf[B23_OFF + i] = make_float2(s, s);
    }
}

__global__ void __launch_bounds__(TPB, 4)
resnet_kernel(const float4* __restrict__ x4, float4* __restrict__ out4, int nthreads)
{
    int t = blockIdx.x * TPB + threadIdx.x;
    if (t >= nthreads) return;

    // 4 points = 12 contiguous floats = 3 aligned float4 loads
    float4 a = x4[3*t + 0];
    float4 b = x4[3*t + 1];
    float4 c = x4[3*t + 2];
    // point-pair packed input: x[pp][k] = (pt_{2pp}[k], pt_{2pp+1}[k])
    u64 xin[2][3] = {
        { pk2(a.x, a.w), pk2(a.y, b.x), pk2(a.z, b.y) },
        { pk2(b.z, c.y), pk2(b.w, c.z), pk2(c.x, c.w) }
    };

    u64 h [2][NH];
    u64 h1[2][NH];

    dense<3 >(OFF_W0, OFF_B0, xin, h);
    dense<NH>(OFF_W1, OFF_B1, h,   h);

#pragma unroll 1
    for (int l = 0; l < NL; l++) {
        dense<NH>(OFF_WR1 + l*100, OFF_BR1 + l*10, h, h1);
        dense_res(OFF_WR3 + l*100, OFF_WR2 + l*100, B23_OFF + l*10, h1, h, h);
    }

    dense<NH>(OFF_W8, OFF_B8, h, h);

    // final [10]->[1], point-pair packed
    u64 oA = ldk(OFF_B9);
    u64 oB = oA;
#pragma unroll
    for (int k = 0; k < NH; k++) {
        u64 wk = ldk(OFF_W9 + k);
        oA = fma2(h[0][k], wk, oA);
        oB = fma2(h[1][k], wk, oB);
    }
    float o0, o1, o2, o3;
    up2(oA, o0, o1);
    up2(oB, o2, o3);
    out4[t] = make_float4(o0, o1, o2, o3);
}

extern "C" void kernel_launch(void* const* d_in, const int* in_sizes, int n_in,
                              void* d_out, int out_size)
{
    // stage raw weights into constant memory (D2D async copies: graph-capturable)
    static const int idx[14] = {1, 2, 3, 4, 5, 6, 7, 8, 9, 10, 11, 12, 13, 14};
    static const int off[14] = {OFF_W0, OFF_B0, OFF_W1, OFF_B1,
                                OFF_WR1, OFF_BR1, OFF_WR2, OFF_BR2, OFF_WR3, OFF_BR3,
                                OFF_W8, OFF_B8, OFF_W9, OFF_B9};
    static const int cnt[14] = {30, 10, 100, 10, 1000, 100, 1000, 100, 1000, 100, 100, 10, 10, 1};
    for (int i = 0; i < 14; i++) {
        cudaMemcpyToSymbolAsync(cw, d_in[idx[i]], (size_t)cnt[i] * sizeof(float),
                                (size_t)off[i] * sizeof(float),
                                cudaMemcpyDeviceToDevice, 0);
    }

    // build duplicated-pair table on device, then stage it into constant memory
    prep_kernel<<<1, 512>>>();
    void* dup_ptr = nullptr;
    cudaGetSymbolAddress(&dup_ptr, dupbuf);
    cudaMemcpyToSymbolAsync(cdup, dup_ptr, CDUP_TOT * sizeof(float2), 0,
                            cudaMemcpyDeviceToDevice, 0);

    int npts     = in_sizes[0] / 3;   // x is [N,3]
    int nthreads = npts / 4;          // 4 points per thread
    int nblocks  = (nthreads + TPB - 1) / TPB;
    resnet_kernel<<<nblocks, TPB>>>((const float4*)d_in[0], (float4*)d_out, nthreads);
}

// round 14
// speedup vs baseline: 4.1354x; 1.5665x over previous
#include <cuda_runtime.h>

typedef unsigned long long u64;

#define NH   10
#define NL   10
#define TPB  128
#define PPT  4

// ---- raw weight layout in cw (float offsets; all 8B-pair offsets even) ----
#define OFF_W0   0
#define OFF_B0   30
#define OFF_W1   40
#define OFF_B1   140
#define OFF_WR1  150
#define OFF_BR1  1150
#define OFF_WR2  1250
#define OFF_BR2  2250
#define OFF_WR3  2350
#define OFF_BR3  3350
#define OFF_W8   3450
#define OFF_B8   3550
#define OFF_W9   3560
#define OFF_B9   3570
#define CW_TOTAL 3572
#define OFF_B23  3572            // precomputed B2+B3, [10][10] raw floats
#define CW_EXT   3672

__constant__ __align__(16) float cw[CW_EXT];
__device__   float b23buf[100];

// ---- helpers ----
// non-duplicated weight PAIR (w_j, w_j+1): ONE warp-uniform 8B constant load (LDCU)
__device__ __forceinline__ u64 ldk(int i) {
    return *reinterpret_cast<const u64*>(&cw[i]);
}
// packed fp32x2 FMA: d = a*b + c, all operands b64 pairs
__device__ __forceinline__ u64 fma2(u64 a, u64 b, u64 c) {
    u64 d; asm("fma.rn.f32x2 %0, %1, %2, %3;" : "=l"(d) : "l"(a), "l"(b), "l"(c)); return d;
}
// duplicate a scalar float into both b64 lanes via TWO alu-pipe adds of opaque zeros.
// z1/z2 are runtime 0 (kernel args) -> ptxas emits IADD3 (alu pipe), not MOV (fma pipe),
// and the two adds write the pair's halves directly (no compose movs).
__device__ __forceinline__ u64 dupa(float h, unsigned z1, unsigned z2) {
    unsigned ui = __float_as_uint(h);
    unsigned lo = ui + z1;
    unsigned hi = ui + z2;
    u64 r; asm("mov.b64 %0, {%1, %2};" : "=l"(r) : "r"(lo), "r"(hi)); return r;
}
// decompose pair into scalar halves (register aliasing; should cost nothing)
__device__ __forceinline__ void up2(u64 v, float& lo, float& hi) {
    asm("mov.b64 {%0, %1}, %2;" : "=f"(lo), "=f"(hi) : "l"(v));
}

// dense + relu: out[p][j] = relu( sum_k h[p][k] * W[k][j] + B[j] )
// j-pair-packed accumulators, scalar h in/out. Reads all h before writing -> in-place safe.
template<int K>
__device__ __forceinline__ void dense(int Wo, int Bo, unsigned z1, unsigned z2,
                                      const float (&h)[PPT][K], float (&out)[PPT][NH])
{
    u64 acc[PPT][NH/2];
    {   // k = 0: bias pair folded as the FMA addend
        u64 hd[PPT];
#pragma unroll
        for (int p = 0; p < PPT; p++) hd[p] = dupa(h[p][0], z1, z2);
#pragma unroll
        for (int j2 = 0; j2 < NH/2; j2++) {
            u64 b = ldk(Bo + 2*j2);
            u64 w = ldk(Wo + 2*j2);
#pragma unroll
            for (int p = 0; p < PPT; p++) acc[p][j2] = fma2(hd[p], w, b);
        }
    }
#pragma unroll
    for (int k = 1; k < K; k++) {
        u64 hd[PPT];
#pragma unroll
        for (int p = 0; p < PPT; p++) hd[p] = dupa(h[p][k], z1, z2);
#pragma unroll
        for (int j2 = 0; j2 < NH/2; j2++) {
            u64 w = ldk(Wo + k*NH + 2*j2);
#pragma unroll
            for (int p = 0; p < PPT; p++) acc[p][j2] = fma2(hd[p], w, acc[p][j2]);
        }
    }
#pragma unroll
    for (int p = 0; p < PPT; p++)
#pragma unroll
        for (int j2 = 0; j2 < NH/2; j2++) {
            float lo, hi; up2(acc[p][j2], lo, hi);
            out[p][2*j2]   = fmaxf(lo, 0.0f);   // FMNMX -> alu pipe
            out[p][2*j2+1] = fmaxf(hi, 0.0f);
        }
}

// residual: out = relu( h1 @ W3 + h0 @ W2 + (B2+B3) ); in-place safe on h0
__device__ __forceinline__ void dense_res(int W3o, int W2o, int B23o, unsigned z1, unsigned z2,
                                          const float (&h1)[PPT][NH],
                                          const float (&h0)[PPT][NH],
                                          float (&out)[PPT][NH])
{
    u64 acc[PPT][NH/2];
    {   // k = 0 of W3, B23 as addend
        u64 hd[PPT];
#pragma unroll
        for (int p = 0; p < PPT; p++) hd[p] = dupa(h1[p][0], z1, z2);
#pragma unroll
        for (int j2 = 0; j2 < NH/2; j2++) {
            u64 b = ldk(B23o + 2*j2);
            u64 w = ldk(W3o + 2*j2);
#pragma unroll
            for (int p = 0; p < PPT; p++) acc[p][j2] = fma2(hd[p], w, b);
        }
    }
#pragma unroll
    for (int k = 1; k < NH; k++) {
        u64 hd[PPT];
#pragma unroll
        for (int p = 0; p < PPT; p++) hd[p] = dupa(h1[p][k], z1, z2);
#pragma unroll
        for (int j2 = 0; j2 < NH/2; j2++) {
            u64 w = ldk(W3o + k*NH + 2*j2);
#pragma unroll
            for (int p = 0; p < PPT; p++) acc[p][j2] = fma2(hd[p], w, acc[p][j2]);
        }
    }
#pragma unroll
    for (int k = 0; k < NH; k++) {
        u64 hd[PPT];
#pragma unroll
        for (int p = 0; p < PPT; p++) hd[p] = dupa(h0[p][k], z1, z2);
#pragma unroll
        for (int j2 = 0; j2 < NH/2; j2++) {
            u64 w = ldk(W2o + k*NH + 2*j2);
#pragma unroll
            for (int p = 0; p < PPT; p++) acc[p][j2] = fma2(hd[p], w, acc[p][j2]);
        }
    }
#pragma unroll
    for (int p = 0; p < PPT; p++)
#pragma unroll
        for (int j2 = 0; j2 < NH/2; j2++) {
            float lo, hi; up2(acc[p][j2], lo, hi);
            out[p][2*j2]   = fmaxf(lo, 0.0f);
            out[p][2*j2+1] = fmaxf(hi, 0.0f);
        }
}

__global__ void prep_kernel()
{
    for (int i = threadIdx.x; i < 100; i += blockDim.x)
        b23buf[i] = cw[OFF_BR2 + i] + cw[OFF_BR3 + i];
}

__global__ void __launch_bounds__(TPB, 4)
resnet_kernel(const float4* __restrict__ x4, float4* __restrict__ out4, int nthreads,
              unsigned z1, unsigned z2)
{
    int t = blockIdx.x * TPB + threadIdx.x;
    if (t >= nthreads) return;

    // 4 points = 12 contiguous floats = 3 aligned float4 loads
    float4 a = x4[3*t + 0];
    float4 b = x4[3*t + 1];
    float4 c = x4[3*t + 2];
    float xin[PPT][3] = {
        {a.x, a.y, a.z},
        {a.w, b.x, b.y},
        {b.z, b.w, c.x},
        {c.y, c.z, c.w}
    };

    float h [PPT][NH];
    float h1[PPT][NH];

    dense<3 >(OFF_W0, OFF_B0, z1, z2, xin, h);
    dense<NH>(OFF_W1, OFF_B1, z1, z2, h,   h);

#pragma unroll 1
    for (int l = 0; l < NL; l++) {
        dense<NH>(OFF_WR1 + l*100, OFF_BR1 + l*10, z1, z2, h, h1);
        dense_res(OFF_WR3 + l*100, OFF_WR2 + l*100, OFF_B23 + l*10, z1, z2, h1, h, h);
    }

    dense<NH>(OFF_W8, OFF_B8, z1, z2, h, h);

    // final [10]->[1], scalar FFMA
    float o[PPT];
    float b9 = cw[OFF_B9];
#pragma unroll
    for (int p = 0; p < PPT; p++) o[p] = b9;
#pragma unroll
    for (int k = 0; k < NH; k++) {
        float wk = cw[OFF_W9 + k];
#pragma unroll
        for (int p = 0; p < PPT; p++) o[p] = fmaf(h[p][k], wk, o[p]);
    }
    out4[t] = make_float4(o[0], o[1], o[2], o[3]);
}

extern "C" void kernel_launch(void* const* d_in, const int* in_sizes, int n_in,
                              void* d_out, int out_size)
{
    // stage raw weights into constant memory (D2D async copies: graph-capturable)
    static const int idx[14] = {1, 2, 3, 4, 5, 6, 7, 8, 9, 10, 11, 12, 13, 14};
    static const int off[14] = {OFF_W0, OFF_B0, OFF_W1, OFF_B1,
                                OFF_WR1, OFF_BR1, OFF_WR2, OFF_BR2, OFF_WR3, OFF_BR3,
                                OFF_W8, OFF_B8, OFF_W9, OFF_B9};
    static const int cnt[14] = {30, 10, 100, 10, 1000, 100, 1000, 100, 1000, 100, 100, 10, 10, 1};
    for (int i = 0; i < 14; i++) {
        cudaMemcpyToSymbolAsync(cw, d_in[idx[i]], (size_t)cnt[i] * sizeof(float),
                                (size_t)off[i] * sizeof(float),
                                cudaMemcpyDeviceToDevice, 0);
    }

    // compute B2+B3 on device, then append into the constant table
    prep_kernel<<<1, 128>>>();
    void* b23_ptr = nullptr;
    cudaGetSymbolAddress(&b23_ptr, b23buf);
    cudaMemcpyToSymbolAsync(cw, b23_ptr, 100 * sizeof(float),
                            (size_t)OFF_B23 * sizeof(float),
                            cudaMemcpyDeviceToDevice, 0);

    int npts     = in_sizes[0] / 3;   // x is [N,3]
    int nthreads = npts / PPT;        // 4 points per thread
    int nblocks  = (nthreads + TPB - 1) / TPB;
    resnet_kernel<<<nblocks, TPB>>>((const float4*)d_in[0], (float4*)d_out, nthreads,
                                    0u, 0u);
}